// round 3
// baseline (speedup 1.0000x reference)
#include <cuda_runtime.h>

// Correlation cost volume:
// out[b,d,h,w] = mean_c( x[b,c,h,w] * y[b,c,h,w-d] )  for w >= d, else 0.
// Shapes: x,y [8,32,256,512] f32; out [8,48,256,512] f32.
//
// Strategy: channel-pair-interleaved smem tiles + packed fma.rn.f32x2.
// Each FFMA2 lane pair = (channel 2k, channel 2k+1) at identical (w, d) ->
// all operand pairs are naturally aligned float2s, no shuffle MOVs at all.

#define BDIM 8
#define CDIM 32
#define C2   (CDIM / 2)      // 16 channel pairs
#define HDIM 256
#define WDIM 512
#define MAXD 48

#define WT   128             // w per block
#define ND   8               // d per thread
#define NW   4               // w per thread
#define NDQ  (MAXD / ND)     // 6 d-groups
#define NWQ  (WT / NW)       // 32 w-groups
#define NTHR (NDQ * NWQ)     // 192 threads

#define YS_S   (WT + MAXD)       // 176 shifted columns per row
#define XS_Q4  (WT / 2)          // 64 float4 per xs row  (2 w per float4)
#define YS_Q4  (YS_S / 2)        // 88 float4 per ys row
#define XS_TOT (C2 * XS_Q4)      // 1024 float4
#define YS_TOT (C2 * YS_Q4)      // 1408 float4
#define SMEM_BYTES ((XS_TOT + YS_TOT) * 16)   // 38912 B

// 16B-granule XOR swizzle: kills the 32B-stride 2-way bank conflicts.
#define SWZ(q) ((q) ^ (((q) >> 3) & 1))

__device__ __forceinline__ float2 ffma2(float2 a, float2 b, float2 c) {
    float2 d;
    asm("fma.rn.f32x2 %0, %1, %2, %3;"
        : "=l"(reinterpret_cast<unsigned long long&>(d))
        : "l"(reinterpret_cast<const unsigned long long&>(a)),
          "l"(reinterpret_cast<const unsigned long long&>(b)),
          "l"(reinterpret_cast<const unsigned long long&>(c)));
    return d;
}

__global__ __launch_bounds__(NTHR, 3)
void corr_kernel(const float* __restrict__ x,
                 const float* __restrict__ y,
                 float* __restrict__ out) {
    extern __shared__ float4 smem4[];
    float4* xs4 = smem4;             // [C2][XS_Q4]  pairs (c0,c1) per w
    float4* ys4 = smem4 + XS_TOT;    // [C2][YS_Q4]  pairs (c0,c1) per s

    const int w0  = blockIdx.x * WT;
    const int h   = blockIdx.y;
    const int b   = blockIdx.z;
    const int tid = threadIdx.x;

    const size_t plane = (size_t)HDIM * WDIM;
    const float* xrow = x + ((size_t)b * CDIM * HDIM + h) * WDIM;
    const float* yrow = y + ((size_t)b * CDIM * HDIM + h) * WDIM;

    // ---- stage x: float4 q in row c2 covers w=2q,2q+1 as (c_even, c_odd) pairs
    for (int i = tid; i < XS_TOT; i += NTHR) {
        int c2 = i >> 6;             // /XS_Q4
        int w2 = i & 63;
        const float* p0 = xrow + (size_t)(2 * c2) * plane + w0 + 2 * w2;
        float2 a = *reinterpret_cast<const float2*>(p0);
        float2 c = *reinterpret_cast<const float2*>(p0 + plane);
        xs4[SWZ(i)] = make_float4(a.x, c.x, a.y, c.y);
    }
    // ---- stage y with left halo of MAXD (zero below w=0) ----
    for (int i = tid; i < YS_TOT; i += NTHR) {
        int c2 = i / YS_Q4;
        int s2 = i - c2 * YS_Q4;
        int gw = w0 - MAXD + 2 * s2;            // even; both lanes <0 iff gw<0
        float2 a = make_float2(0.f, 0.f), c = make_float2(0.f, 0.f);
        if (gw >= 0) {
            const float* p0 = yrow + (size_t)(2 * c2) * plane + gw;
            a = *reinterpret_cast<const float2*>(p0);
            c = *reinterpret_cast<const float2*>(p0 + plane);
        }
        ys4[SWZ(i)] = make_float4(a.x, c.x, a.y, c.y);
    }
    __syncthreads();

    const int wq = tid & (NWQ - 1);   // 0..31  -> w = w0 + 4*wq + j
    const int dq = tid >> 5;          // 0..5   -> d = 8*dq + i
    const int xb = 2 * wq;                     // in-row float4 base for x
    const int yb = 20 + 2 * wq - 4 * dq;       // in-row float4 base for y
    // float4 (yb+k) covers shifted cols s = 2*(yb+k), 2*(yb+k)+1;
    // s0 = 2*yb = 40+4wq-8dq = sb-8 with sb = MAXD+4wq-8dq.

    float2 acc[ND][NW];
    #pragma unroll
    for (int i = 0; i < ND; i++)
        #pragma unroll
        for (int j = 0; j < NW; j++) acc[i][j] = make_float2(0.f, 0.f);

    #pragma unroll 4
    for (int c2 = 0; c2 < C2; c2++) {
        float4 xv0 = xs4[SWZ(c2 * XS_Q4 + xb)];
        float4 xv1 = xs4[SWZ(c2 * XS_Q4 + xb + 1)];
        float2 x2[NW] = { make_float2(xv0.x, xv0.y), make_float2(xv0.z, xv0.w),
                          make_float2(xv1.x, xv1.y), make_float2(xv1.z, xv1.w) };

        float2 yw[12];
        #pragma unroll
        for (int k = 0; k < 6; k++) {
            float4 t = ys4[SWZ(c2 * YS_Q4 + yb + k)];
            yw[2 * k]     = make_float2(t.x, t.y);
            yw[2 * k + 1] = make_float2(t.z, t.w);
        }

        // acc[i][j] += x2[j] (.) y2[sb + j - i]; local index = 8 + j - i
        #pragma unroll
        for (int i = 0; i < ND; i++)
            #pragma unroll
            for (int j = 0; j < NW; j++)
                acc[i][j] = ffma2(x2[j], yw[8 + j - i], acc[i][j]);
    }

    // ---- epilogue: horizontal add over channel parity, mean, mask, STG.128 ----
    const float scale = 1.0f / (float)CDIM;
    const int wbase = w0 + NW * wq;
    #pragma unroll
    for (int i = 0; i < ND; i++) {
        const int d = ND * dq + i;
        float4 o;
        o.x = (wbase + 0 >= d) ? (acc[i][0].x + acc[i][0].y) * scale : 0.f;
        o.y = (wbase + 1 >= d) ? (acc[i][1].x + acc[i][1].y) * scale : 0.f;
        o.z = (wbase + 2 >= d) ? (acc[i][2].x + acc[i][2].y) * scale : 0.f;
        o.w = (wbase + 3 >= d) ? (acc[i][3].x + acc[i][3].y) * scale : 0.f;
        *reinterpret_cast<float4*>(
            out + (((size_t)b * MAXD + d) * HDIM + h) * WDIM + wbase) = o;
    }
}

extern "C" void kernel_launch(void* const* d_in, const int* in_sizes, int n_in,
                              void* d_out, int out_size) {
    const float* x = (const float*)d_in[0];
    const float* y = (const float*)d_in[1];
    float* out = (float*)d_out;

    cudaFuncSetAttribute(corr_kernel,
                         cudaFuncAttributeMaxDynamicSharedMemorySize,
                         (int)SMEM_BYTES);

    dim3 grid(WDIM / WT, HDIM, BDIM);   // (4, 256, 8) = 8192 blocks
    corr_kernel<<<grid, NTHR, SMEM_BYTES>>>(x, y, out);
}

// round 4
// speedup vs baseline: 1.3428x; 1.3428x over previous
#include <cuda_runtime.h>

// Correlation cost volume:
// out[b,d,h,w] = mean_c( x[b,c,h,w] * y[b,c,h,w-d] )  for w >= d, else 0.
// Shapes: x,y [8,32,256,512] f32; out [8,48,256,512] f32.
//
// R4: R2 tiling (conflict-free, no swizzle) + software-pipelined c-loop
// (register double-buffer, loads issued one iteration ahead) + single
// explicit construction of the 9 odd-shift y pairs (18 MOVs/iter).

#define BDIM 8
#define CDIM 32
#define HDIM 256
#define WDIM 512
#define MAXD 48

#define WT   256            // w-tile per block
#define DT   16             // d per thread
#define NDQ  (MAXD / DT)    // 3 d-groups
#define NWQ  (WT / 4)       // 64 w-groups (4 w per thread)
#define NTHR (NDQ * NWQ)    // 192 threads
#define YS_W (WT + MAXD)    // 304 floats per y row (48-col halo)

#define SMEM_BYTES ((CDIM * WT + CDIM * YS_W) * sizeof(float))  // 70 KB

__device__ __forceinline__ float2 ffma2(float2 a, float2 b, float2 c) {
    float2 d;
    asm("fma.rn.f32x2 %0, %1, %2, %3;"
        : "=l"(reinterpret_cast<unsigned long long&>(d))
        : "l"(reinterpret_cast<const unsigned long long&>(a)),
          "l"(reinterpret_cast<const unsigned long long&>(b)),
          "l"(reinterpret_cast<const unsigned long long&>(c)));
    return d;
}

__global__ __launch_bounds__(NTHR, 3)   // 3 blocks/SM -> 18 warps, <=113 regs
void corr_kernel(const float* __restrict__ x,
                 const float* __restrict__ y,
                 float* __restrict__ out) {
    extern __shared__ float smem[];
    float* xs = smem;                 // [CDIM][WT]
    float* ys = smem + CDIM * WT;     // [CDIM][YS_W]

    const int w0  = blockIdx.x * WT;
    const int h   = blockIdx.y;
    const int b   = blockIdx.z;
    const int tid = threadIdx.x;

    const size_t plane = (size_t)HDIM * WDIM;
    const float* xrow = x + ((size_t)b * CDIM * HDIM + h) * WDIM;
    const float* yrow = y + ((size_t)b * CDIM * HDIM + h) * WDIM;

    // ---- stage x tile (float4, coalesced, conflict-free) ----
    #pragma unroll 4
    for (int i = tid; i < CDIM * (WT / 4); i += NTHR) {
        int c = i / (WT / 4);
        int v = i % (WT / 4);
        float4 val = *reinterpret_cast<const float4*>(xrow + c * plane + w0 + v * 4);
        *reinterpret_cast<float4*>(&xs[c * WT + v * 4]) = val;
    }
    // ---- stage y tile with left halo of MAXD (zero below w=0) ----
    #pragma unroll 4
    for (int i = tid; i < CDIM * (YS_W / 4); i += NTHR) {
        int c = i / (YS_W / 4);
        int v = i % (YS_W / 4);
        int gw = w0 - MAXD + v * 4;
        float4 val = make_float4(0.f, 0.f, 0.f, 0.f);
        if (gw >= 0)
            val = *reinterpret_cast<const float4*>(yrow + c * plane + gw);
        *reinterpret_cast<float4*>(&ys[c * YS_W + v * 4]) = val;
    }
    __syncthreads();

    const int wq = tid % NWQ;             // 0..63
    const int dq = tid / NWQ;             // 0..2
    const int hb = MAXD + 4 * wq - DT * dq;  // 4-aligned; 16..300

    float2 acc[DT][2];
    #pragma unroll
    for (int i = 0; i < DT; i++) {
        acc[i][0] = make_float2(0.f, 0.f);
        acc[i][1] = make_float2(0.f, 0.f);
    }

    // Double-buffered operands: xbuf[p], ybuf[p][0..4]
    float4 xbuf[2];
    float4 ybuf[2][5];

    // prologue: load c = 0
    {
        const float* xsr = &xs[0 * WT];
        const float* ysr = &ys[0 * YS_W];
        xbuf[0] = *reinterpret_cast<const float4*>(&xsr[wq * 4]);
        #pragma unroll
        for (int k = 0; k < 5; k++)
            ybuf[0][k] = *reinterpret_cast<const float4*>(&ysr[hb - 16 + 4 * k]);
    }

    #pragma unroll 4
    for (int c = 0; c < CDIM; c++) {
        const int cur = c & 1;
        const int nxt = cur ^ 1;

        // ---- prefetch iteration c+1 (clamped on last iter; harmless reload) ----
        {
            const int cn = (c + 1 < CDIM) ? (c + 1) : (CDIM - 1);
            const float* xsr = &xs[cn * WT];
            const float* ysr = &ys[cn * YS_W];
            xbuf[nxt] = *reinterpret_cast<const float4*>(&xsr[wq * 4]);
            #pragma unroll
            for (int k = 0; k < 5; k++)
                ybuf[nxt][k] = *reinterpret_cast<const float4*>(&ysr[hb - 16 + 4 * k]);
        }

        // ---- compute on buffer `cur` ----
        const float4 xv = xbuf[cur];
        const float2 x01 = make_float2(xv.x, xv.y);
        const float2 x23 = make_float2(xv.z, xv.w);

        // aligned pairs yp[t] = (ya[2t], ya[2t+1]) live inside ybuf float4s
        float2 yp[10];
        #pragma unroll
        for (int k = 0; k < 5; k++) {
            yp[2 * k]     = make_float2(ybuf[cur][k].x, ybuf[cur][k].y);
            yp[2 * k + 1] = make_float2(ybuf[cur][k].z, ybuf[cur][k].w);
        }
        // shifted pairs zp[t] = (ya[2t+1], ya[2t+2]) built once: 18 MOVs
        float2 zp[9];
        #pragma unroll
        for (int t = 0; t < 9; t++) {
            if ((t & 1) == 0)   // intra-float4: (.y, .z)
                zp[t] = make_float2(ybuf[cur][t >> 1].y, ybuf[cur][t >> 1].z);
            else                // cross-float4: (.w, .x)
                zp[t] = make_float2(ybuf[cur][t >> 1].w, ybuf[cur][(t >> 1) + 1].x);
        }

        // acc[i][j] += x[j] * ya[16 + j - i]
        #pragma unroll
        for (int i = 0; i < DT; i++) {
            float2 ylo, yhi;
            if ((i & 1) == 0) { ylo = yp[(16 - i) >> 1]; yhi = yp[(18 - i) >> 1]; }
            else              { ylo = zp[(15 - i) >> 1]; yhi = zp[(17 - i) >> 1]; }
            acc[i][0] = ffma2(x01, ylo, acc[i][0]);
            acc[i][1] = ffma2(x23, yhi, acc[i][1]);
        }
    }

    // ---- epilogue: mean over C, zero invalid cols (w < d), STG.128 ----
    const float scale = 1.0f / (float)CDIM;
    const int wbase = w0 + wq * 4;
    #pragma unroll
    for (int i = 0; i < DT; i++) {
        const int d = dq * DT + i;
        float4 o;
        o.x = (wbase + 0 >= d) ? acc[i][0].x * scale : 0.f;
        o.y = (wbase + 1 >= d) ? acc[i][0].y * scale : 0.f;
        o.z = (wbase + 2 >= d) ? acc[i][1].x * scale : 0.f;
        o.w = (wbase + 3 >= d) ? acc[i][1].y * scale : 0.f;
        *reinterpret_cast<float4*>(
            out + (((size_t)b * MAXD + d) * HDIM + h) * WDIM + wbase) = o;
    }
}

extern "C" void kernel_launch(void* const* d_in, const int* in_sizes, int n_in,
                              void* d_out, int out_size) {
    const float* x = (const float*)d_in[0];
    const float* y = (const float*)d_in[1];
    float* out = (float*)d_out;

    cudaFuncSetAttribute(corr_kernel,
                         cudaFuncAttributeMaxDynamicSharedMemorySize,
                         (int)SMEM_BYTES);

    dim3 grid(WDIM / WT, HDIM, BDIM);   // (2, 256, 8) = 4096 blocks
    corr_kernel<<<grid, NTHR, SMEM_BYTES>>>(x, y, out);
}

// round 6
// speedup vs baseline: 1.6911x; 1.2594x over previous
#include <cuda_runtime.h>
#include <cstdint>

// Correlation cost volume via banded tf32 mma.sync (arch-portable PTX, no
// tcgen05 -- harness ptxas targets sm_103 without the 'a' feature).
// out[b,d,h,w] = mean_c( x[b,c,h,w] * y[b,c,h,w-d] ), 0 where w<d (exact via
// zero-padded halo).
// Per (b,h,wtile=128): A[i,k]=x[k,w0+i] (128x32), B[s,k]=y[k,w0-48+s] (176x32),
// P = A.B^T. Warp m owns rows [16m,16m+16), needs only s in [16m, 16m+64):
// 8 n-tiles of m16n8k8. d = 48 - (s - i); epilogue stores to stage[48-d][i]
// so the gather per d is a contiguous row.

#define BDIM 8
#define CDIM 32
#define HDIM 256
#define WDIM 512
#define MAXD 48

#define MT   128
#define NT   176
#define NTHR 256

#define AP 136                 // A pitch (words): bank = 8c + r, conflict-free
#define BP 184                 // B pitch (words): bank = 24c + n, conflict-free
#define SP 136                 // stage pitch (words): row-contig reads
#define A_WORDS (CDIM * AP)    // 4352
#define B_WORDS (CDIM * BP)    // 5888
#define SMEM_BYTES ((A_WORDS + B_WORDS) * 4)   // 40960 B (stage reuses A/B)

__device__ __forceinline__ uint32_t f2tf32(float v) {
    uint32_t r;
    asm("cvt.rna.tf32.f32 %0, %1;" : "=r"(r) : "f"(v));
    return r;
}

__device__ __forceinline__ void mma_tf32(float* c, const uint32_t* a, const uint32_t* b) {
    asm volatile(
        "mma.sync.aligned.m16n8k8.row.col.f32.tf32.tf32.f32 "
        "{%0,%1,%2,%3}, {%4,%5,%6,%7}, {%8,%9}, {%0,%1,%2,%3};"
        : "+f"(c[0]), "+f"(c[1]), "+f"(c[2]), "+f"(c[3])
        : "r"(a[0]), "r"(a[1]), "r"(a[2]), "r"(a[3]), "r"(b[0]), "r"(b[1]));
}

__global__ __launch_bounds__(NTHR, 3)
void corr_mma(const float* __restrict__ x, const float* __restrict__ y,
              float* __restrict__ out) {
    extern __shared__ uint32_t smem[];
    uint32_t* As = smem;             // [CDIM][AP]  As[k][i] = tf32(x[k, w0+i])
    uint32_t* Bs = smem + A_WORDS;   // [CDIM][BP]  Bs[k][s] = tf32(y[k, w0-48+s])
    float*    St = reinterpret_cast<float*>(smem);   // stage [49][SP], post-sync

    const int tid  = threadIdx.x;
    const int warp = tid >> 5, lane = tid & 31;
    const int w0 = blockIdx.x * MT;
    const int h  = blockIdx.y;
    const int b  = blockIdx.z;

    const size_t plane = (size_t)HDIM * WDIM;
    const float* xr = x + ((size_t)b * CDIM * HDIM + h) * WDIM;
    const float* yr = y + ((size_t)b * CDIM * HDIM + h) * WDIM;

    // ---- stage A^T: 32 rows x 128 floats, coalesced LDG.128, contig STS ----
    for (int i = tid; i < CDIM * (MT / 4); i += NTHR) {
        const int k = i >> 5, v = (i & 31) * 4;
        float4 t = *reinterpret_cast<const float4*>(xr + k * plane + w0 + v);
        uint32_t* d = &As[k * AP + v];
        d[0] = f2tf32(t.x); d[1] = f2tf32(t.y); d[2] = f2tf32(t.z); d[3] = f2tf32(t.w);
    }
    // ---- stage B^T: 32 rows x 176 floats, zero-pad left halo ----
    for (int i = tid; i < CDIM * (NT / 4); i += NTHR) {
        const int k = i / (NT / 4), v = (i % (NT / 4)) * 4;
        const int gw = w0 - MAXD + v;       // 4-aligned; all 4 lanes same sign
        float4 t = make_float4(0.f, 0.f, 0.f, 0.f);
        if (gw >= 0)
            t = *reinterpret_cast<const float4*>(yr + k * plane + gw);
        uint32_t* d = &Bs[k * BP + v];
        d[0] = f2tf32(t.x); d[1] = f2tf32(t.y); d[2] = f2tf32(t.z); d[3] = f2tf32(t.w);
    }
    __syncthreads();

    // ---- banded MMA: warp owns m-tile rows [i0, i0+16), n-tiles s=[i0, i0+64) ----
    const int i0 = 16 * warp;
    const int r  = lane >> 2;     // 0..7
    const int cq = lane & 3;      // 0..3

    float acc[8][4];
    #pragma unroll
    for (int t = 0; t < 8; t++)
        #pragma unroll
        for (int q = 0; q < 4; q++) acc[t][q] = 0.f;

    #pragma unroll
    for (int ks = 0; ks < 4; ks++) {
        const int k0 = 8 * ks;
        uint32_t a[4];
        a[0] = As[(k0 + cq)     * AP + i0 + r];
        a[1] = As[(k0 + cq)     * AP + i0 + r + 8];
        a[2] = As[(k0 + cq + 4) * AP + i0 + r];
        a[3] = As[(k0 + cq + 4) * AP + i0 + r + 8];
        #pragma unroll
        for (int t = 0; t < 8; t++) {
            uint32_t bfr[2];
            const int s0 = i0 + 8 * t;
            bfr[0] = Bs[(k0 + cq)     * BP + s0 + r];   // b0: row=k=lane&3? see map
            bfr[1] = Bs[(k0 + cq + 4) * BP + s0 + r];
            // NOTE: B frag mapping is (k = lane&3 [+4], n = lane>>2) -> uses cq as k, r as n
            mma_tf32(acc[t], a, bfr);
        }
    }
    __syncthreads();   // all smem reads done; reuse for stage

    // ---- scatter accumulators into shift-normalized stage[u = 48-d][i] ----
    // c-frag element (row re, col sl): c0 (r, 8t+2cq), c1 (r, 8t+2cq+1),
    // c2 (r+8, ...), c3 (r+8, ...+1). u = sl - re, keep 1 <= u <= 48.
    #pragma unroll
    for (int t = 0; t < 8; t++) {
        #pragma unroll
        for (int q = 0; q < 4; q++) {
            const int re = r + (q >= 2 ? 8 : 0);
            const int sl = 8 * t + 2 * cq + (q & 1);
            const int u  = sl - re;
            if (u >= 1 && u <= MAXD)
                St[u * SP + i0 + re] = acc[t][q];
        }
    }
    __syncthreads();

    // ---- gather: row u = 48-d is contiguous in i; LDS.128 + STG.128 ----
    const float scale = 1.0f / (float)CDIM;
    const int iq = 4 * (tid & 31);
    const int db = tid >> 5;
    #pragma unroll
    for (int k = 0; k < 6; k++) {
        const int d = db + 8 * k;
        const int u = MAXD - d;
        float4 v = *reinterpret_cast<const float4*>(&St[u * SP + iq]);
        v.x *= scale; v.y *= scale; v.z *= scale; v.w *= scale;
        *reinterpret_cast<float4*>(
            out + (((size_t)b * MAXD + d) * HDIM + h) * WDIM + w0 + iq) = v;
    }
}

extern "C" void kernel_launch(void* const* d_in, const int* in_sizes, int n_in,
                              void* d_out, int out_size) {
    const float* x = (const float*)d_in[0];
    const float* y = (const float*)d_in[1];
    float* out = (float*)d_out;

    cudaFuncSetAttribute(corr_mma,
                         cudaFuncAttributeMaxDynamicSharedMemorySize, SMEM_BYTES);

    dim3 grid(WDIM / MT, HDIM, BDIM);   // (4, 256, 8) = 8192 blocks
    corr_mma<<<grid, NTHR, SMEM_BYTES>>>(x, y, out);
}

// round 7
// speedup vs baseline: 2.5828x; 1.5273x over previous
#include <cuda_runtime.h>
#include <cstdint>

// Correlation cost volume via banded tf32 mma.sync, software-pipelined over h
// with cp.async double-buffered staging.
// out[b,d,h,w] = mean_c( x[b,c,h,w] * y[b,c,h,w-d] ), 0 where w<d (exact via
// zero-padded halo; cp.async zfill).
// Per (b,h,wtile=128): A[i,k]=x[k,w0+i] (128x32), B[s,k]=y[k,w0-48+s] (176x32),
// P = A.B^T banded; warp m computes rows [16m,16m+16) x cols [16m,16m+64).
// d = 48-(s-i); epilogue stages to St[48-d][i] so per-d gather is a contig row.

#define BDIM 8
#define CDIM 32
#define HDIM 256
#define WDIM 512
#define MAXD 48

#define MT   128
#define NT   176
#define NTHR 256
#define HC   8                  // h rows per block

#define AP 136                  // A pitch (words), frag loads conflict-free
#define BP 184                  // B pitch (words), frag loads conflict-free
#define SP 136                  // stage pitch (words)
#define A_WORDS (CDIM * AP)     // 4352
#define B_WORDS (CDIM * BP)     // 5888
#define BUF_WORDS (A_WORDS + B_WORDS)       // 10240
#define ST_OFF  (2 * BUF_WORDS)             // 20480
#define ST_WORDS ((MAXD + 1) * SP)          // 6664
#define SMEM_BYTES ((ST_OFF + ST_WORDS) * 4)  // 108576 B

#define A_CHUNKS (CDIM * (MT / 4))   // 1024 16B chunks
#define B_CHUNKS (CDIM * (NT / 4))   // 1408

__device__ __forceinline__ uint32_t f2tf32(float v) {
    uint32_t r;
    asm("cvt.rna.tf32.f32 %0, %1;" : "=r"(r) : "f"(v));
    return r;
}
__device__ __forceinline__ uint32_t smem_u32(const void* p) {
    uint32_t a;
    asm("{ .reg .u64 t; cvta.to.shared.u64 t, %1; cvt.u32.u64 %0, t; }" : "=r"(a) : "l"(p));
    return a;
}
__device__ __forceinline__ void cp16(uint32_t dst, const void* src, int src_sz) {
    asm volatile("cp.async.cg.shared.global [%0], [%1], 16, %2;"
                 :: "r"(dst), "l"(src), "r"(src_sz) : "memory");
}
__device__ __forceinline__ void mma_tf32(float* c, const uint32_t* a, const uint32_t* b) {
    asm volatile(
        "mma.sync.aligned.m16n8k8.row.col.f32.tf32.tf32.f32 "
        "{%0,%1,%2,%3}, {%4,%5,%6,%7}, {%8,%9}, {%0,%1,%2,%3};"
        : "+f"(c[0]), "+f"(c[1]), "+f"(c[2]), "+f"(c[3])
        : "r"(a[0]), "r"(a[1]), "r"(a[2]), "r"(a[3]), "r"(b[0]), "r"(b[1]));
}

__global__ __launch_bounds__(NTHR, 2)
void corr_mma(const float* __restrict__ x, const float* __restrict__ y,
              float* __restrict__ out) {
    extern __shared__ uint32_t smem[];
    const uint32_t sb = smem_u32(smem);

    const int tid  = threadIdx.x;
    const int warp = tid >> 5, lane = tid & 31;
    const int w0    = blockIdx.x * MT;
    const int hbase = blockIdx.y * HC;
    const int b     = blockIdx.z;

    const size_t plane = (size_t)HDIM * WDIM;
    const float* xb = x + (size_t)b * CDIM * plane;
    const float* yb = y + (size_t)b * CDIM * plane;

    // ---- cp.async staging of one (A,B) tile pair for row h into buffer pb ----
    auto issue_stage = [&](int pb, int h) {
        const float* xr = xb + (size_t)h * WDIM;
        const float* yr = yb + (size_t)h * WDIM;
        const uint32_t abase = sb + (pb * BUF_WORDS) * 4;
        const uint32_t bbase = abase + A_WORDS * 4;
        #pragma unroll 2
        for (int i = tid; i < A_CHUNKS + B_CHUNKS; i += NTHR) {
            if (i < A_CHUNKS) {
                const int k = i >> 5, v = (i & 31) << 2;
                cp16(abase + (k * AP + v) * 4, xr + k * plane + w0 + v, 16);
            } else {
                const int j = i - A_CHUNKS;
                const int k = j / (NT / 4), v = (j % (NT / 4)) << 2;
                const int gw = w0 - MAXD + v;
                cp16(bbase + (k * BP + v) * 4,
                     yr + k * plane + (gw >= 0 ? gw : 0), gw >= 0 ? 16 : 0);
            }
        }
    };

    // prologue: stage h0
    issue_stage(0, hbase);
    asm volatile("cp.async.commit_group;" ::: "memory");

    const int i0 = 16 * warp;
    const int r  = lane >> 2;     // 0..7
    const int cq = lane & 3;      // 0..3
    float* St = reinterpret_cast<float*>(smem + ST_OFF);

    for (int hh = 0; hh < HC; hh++) {
        const int p = hh & 1;
        const int h = hbase + hh;

        if (hh + 1 < HC) {
            issue_stage(p ^ 1, h + 1);
            asm volatile("cp.async.commit_group;" ::: "memory");
            asm volatile("cp.async.wait_group 1;" ::: "memory");
        } else {
            asm volatile("cp.async.wait_group 0;" ::: "memory");
        }
        __syncthreads();

        // ---- in-place fp32 -> tf32(.rna) convert of buffer p ----
        uint32_t* buf = smem + p * BUF_WORDS;
        #pragma unroll 4
        for (int i = tid; i < BUF_WORDS / 4; i += NTHR) {
            float4 t = reinterpret_cast<float4*>(buf)[i];
            uint4 u;
            u.x = f2tf32(t.x); u.y = f2tf32(t.y);
            u.z = f2tf32(t.z); u.w = f2tf32(t.w);
            reinterpret_cast<uint4*>(buf)[i] = u;
        }
        __syncthreads();

        // ---- banded MMA from buffer p ----
        const uint32_t* As = buf;             // [CDIM][AP]
        const uint32_t* Bs = buf + A_WORDS;   // [CDIM][BP]

        float acc[8][4];
        #pragma unroll
        for (int t = 0; t < 8; t++)
            #pragma unroll
            for (int q = 0; q < 4; q++) acc[t][q] = 0.f;

        #pragma unroll
        for (int ks = 0; ks < 4; ks++) {
            const int k0 = 8 * ks;
            uint32_t a[4];
            a[0] = As[(k0 + cq)     * AP + i0 + r];
            a[1] = As[(k0 + cq)     * AP + i0 + r + 8];
            a[2] = As[(k0 + cq + 4) * AP + i0 + r];
            a[3] = As[(k0 + cq + 4) * AP + i0 + r + 8];
            #pragma unroll
            for (int t = 0; t < 8; t++) {
                uint32_t bfr[2];
                const int s0 = i0 + 8 * t;
                bfr[0] = Bs[(k0 + cq)     * BP + s0 + r];
                bfr[1] = Bs[(k0 + cq + 4) * BP + s0 + r];
                mma_tf32(acc[t], a, bfr);
            }
        }

        // ---- scatter into shift-normalized stage St[u = 48-d][i] ----
        #pragma unroll
        for (int t = 0; t < 8; t++) {
            #pragma unroll
            for (int q = 0; q < 4; q++) {
                const int re = r + (q >= 2 ? 8 : 0);
                const int sl = 8 * t + 2 * cq + (q & 1);
                const int u  = sl - re;
                if (u >= 1 && u <= MAXD)
                    St[u * SP + i0 + re] = acc[t][q];
            }
        }
        __syncthreads();

        // ---- gather row u = 48-d (contiguous) + coalesced STG.128 ----
        const float scale = 1.0f / (float)CDIM;
        const int iq = 4 * lane;
        #pragma unroll
        for (int k = 0; k < 6; k++) {
            const int d = warp + 8 * k;
            float4 v = *reinterpret_cast<const float4*>(&St[(MAXD - d) * SP + iq]);
            v.x *= scale; v.y *= scale; v.z *= scale; v.w *= scale;
            *reinterpret_cast<float4*>(
                out + (((size_t)b * MAXD + d) * HDIM + h) * WDIM + w0 + iq) = v;
        }
        // next iteration's post-wait __syncthreads orders gather (St reads)
        // before the next scatter; MMA smem reads of buf p precede the
        // post-scatter barrier, so cp.async refill of buf p (issued next
        // iteration) cannot race them.
    }
}

extern "C" void kernel_launch(void* const* d_in, const int* in_sizes, int n_in,
                              void* d_out, int out_size) {
    const float* x = (const float*)d_in[0];
    const float* y = (const float*)d_in[1];
    float* out = (float*)d_out;

    cudaFuncSetAttribute(corr_mma,
                         cudaFuncAttributeMaxDynamicSharedMemorySize, SMEM_BYTES);

    dim3 grid(WDIM / MT, HDIM / HC, BDIM);   // (4, 32, 8) = 1024 blocks
    corr_mma<<<grid, NTHR, SMEM_BYTES>>>(x, y, out);
}

// round 8
// speedup vs baseline: 3.0607x; 1.1850x over previous
#include <cuda_runtime.h>
#include <cstdint>

// Correlation cost volume via banded tf32 mma.sync, software-pipelined over h
// with cp.async double-buffered staging. tf32(.rna) conversion folded into the
// MMA fragment loads (no separate smem convert pass).
// out[b,d,h,w] = mean_c( x[b,c,h,w] * y[b,c,h,w-d] ), 0 where w<d (exact via
// zero-padded halo; cp.async zfill).
// Per (b,h,wtile=128): A[i,k]=x[k,w0+i] (128x32), B[s,k]=y[k,w0-48+s] (176x32),
// P = A.B^T banded; warp m computes rows [16m,16m+16) x cols [16m,16m+64).
// d = 48-(s-i); epilogue stages to St[48-d][i] so per-d gather is a contig row.

#define BDIM 8
#define CDIM 32
#define HDIM 256
#define WDIM 512
#define MAXD 48

#define MT   128
#define NT   176
#define NTHR 256
#define HC   8                  // h rows per block

#define AP 136                  // A pitch (words), frag loads conflict-free
#define BP 184                  // B pitch (words), frag loads conflict-free
#define SP 136                  // stage pitch (words)
#define A_WORDS (CDIM * AP)     // 4352
#define B_WORDS (CDIM * BP)     // 5888
#define BUF_WORDS (A_WORDS + B_WORDS)       // 10240
#define ST_OFF  (2 * BUF_WORDS)             // 20480
#define ST_WORDS ((MAXD + 1) * SP)          // 6664
#define SMEM_BYTES ((ST_OFF + ST_WORDS) * 4)  // 108576 B

#define A_CHUNKS (CDIM * (MT / 4))   // 1024 16B chunks
#define B_CHUNKS (CDIM * (NT / 4))   // 1408

__device__ __forceinline__ uint32_t f2tf32(float v) {
    uint32_t r;
    asm("cvt.rna.tf32.f32 %0, %1;" : "=r"(r) : "f"(v));
    return r;
}
__device__ __forceinline__ uint32_t smem_u32(const void* p) {
    uint32_t a;
    asm("{ .reg .u64 t; cvta.to.shared.u64 t, %1; cvt.u32.u64 %0, t; }" : "=r"(a) : "l"(p));
    return a;
}
__device__ __forceinline__ void cp16(uint32_t dst, const void* src, int src_sz) {
    asm volatile("cp.async.cg.shared.global [%0], [%1], 16, %2;"
                 :: "r"(dst), "l"(src), "r"(src_sz) : "memory");
}
__device__ __forceinline__ void mma_tf32(float* c, const uint32_t* a, const uint32_t* b) {
    asm volatile(
        "mma.sync.aligned.m16n8k8.row.col.f32.tf32.tf32.f32 "
        "{%0,%1,%2,%3}, {%4,%5,%6,%7}, {%8,%9}, {%0,%1,%2,%3};"
        : "+f"(c[0]), "+f"(c[1]), "+f"(c[2]), "+f"(c[3])
        : "r"(a[0]), "r"(a[1]), "r"(a[2]), "r"(a[3]), "r"(b[0]), "r"(b[1]));
}

__global__ __launch_bounds__(NTHR, 2)
void corr_mma(const float* __restrict__ x, const float* __restrict__ y,
              float* __restrict__ out) {
    extern __shared__ float smem[];
    const uint32_t sb = smem_u32(smem);

    const int tid  = threadIdx.x;
    const int warp = tid >> 5, lane = tid & 31;
    const int w0    = blockIdx.x * MT;
    const int hbase = blockIdx.y * HC;
    const int b     = blockIdx.z;

    const size_t plane = (size_t)HDIM * WDIM;
    const float* xb = x + (size_t)b * CDIM * plane;
    const float* yb = y + (size_t)b * CDIM * plane;

    // ---- cp.async staging of one (A,B) fp32 tile pair into buffer pb ----
    auto issue_stage = [&](int pb, int h) {
        const float* xr = xb + (size_t)h * WDIM;
        const float* yr = yb + (size_t)h * WDIM;
        const uint32_t abase = sb + (pb * BUF_WORDS) * 4;
        const uint32_t bbase = abase + A_WORDS * 4;
        #pragma unroll 2
        for (int i = tid; i < A_CHUNKS + B_CHUNKS; i += NTHR) {
            if (i < A_CHUNKS) {
                const int k = i >> 5, v = (i & 31) << 2;
                cp16(abase + (k * AP + v) * 4, xr + k * plane + w0 + v, 16);
            } else {
                const int j = i - A_CHUNKS;
                const int k = j / (NT / 4), v = (j % (NT / 4)) << 2;
                const int gw = w0 - MAXD + v;
                cp16(bbase + (k * BP + v) * 4,
                     yr + k * plane + (gw >= 0 ? gw : 0), gw >= 0 ? 16 : 0);
            }
        }
    };

    // prologue: stage h0
    issue_stage(0, hbase);
    asm volatile("cp.async.commit_group;" ::: "memory");

    const int i0 = 16 * warp;
    const int r  = lane >> 2;     // 0..7
    const int cq = lane & 3;      // 0..3
    float* St = smem + ST_OFF;

    for (int hh = 0; hh < HC; hh++) {
        const int p = hh & 1;
        const int h = hbase + hh;

        if (hh + 1 < HC) {
            issue_stage(p ^ 1, h + 1);
            asm volatile("cp.async.commit_group;" ::: "memory");
            asm volatile("cp.async.wait_group 1;" ::: "memory");
        } else {
            asm volatile("cp.async.wait_group 0;" ::: "memory");
        }
        __syncthreads();   // data of buffer p visible; St free (prev gather done)

        // ---- banded MMA from buffer p; cvt.rna folded into fragment loads ----
        const float* As = smem + p * BUF_WORDS;   // [CDIM][AP] fp32
        const float* Bs = As + A_WORDS;           // [CDIM][BP] fp32

        float acc[8][4];
        #pragma unroll
        for (int t = 0; t < 8; t++)
            #pragma unroll
            for (int q = 0; q < 4; q++) acc[t][q] = 0.f;

        #pragma unroll
        for (int ks = 0; ks < 4; ks++) {
            const int k0 = 8 * ks;
            uint32_t a[4];
            a[0] = f2tf32(As[(k0 + cq)     * AP + i0 + r]);
            a[1] = f2tf32(As[(k0 + cq)     * AP + i0 + r + 8]);
            a[2] = f2tf32(As[(k0 + cq + 4) * AP + i0 + r]);
            a[3] = f2tf32(As[(k0 + cq + 4) * AP + i0 + r + 8]);
            #pragma unroll
            for (int t = 0; t < 8; t++) {
                const int s0 = i0 + 8 * t;
                uint32_t bfr[2];
                bfr[0] = f2tf32(Bs[(k0 + cq)     * BP + s0 + r]);
                bfr[1] = f2tf32(Bs[(k0 + cq + 4) * BP + s0 + r]);
                mma_tf32(acc[t], a, bfr);
            }
        }

        // ---- scatter into shift-normalized stage St[u = 48-d][i] ----
        #pragma unroll
        for (int t = 0; t < 8; t++) {
            #pragma unroll
            for (int q = 0; q < 4; q++) {
                const int re = r + (q >= 2 ? 8 : 0);
                const int sl = 8 * t + 2 * cq + (q & 1);
                const int u  = sl - re;
                if (u >= 1 && u <= MAXD)
                    St[u * SP + i0 + re] = acc[t][q];
            }
        }
        __syncthreads();

        // ---- gather row u = 48-d (contiguous) + coalesced STG.128 ----
        const float scale = 1.0f / (float)CDIM;
        const int iq = 4 * lane;
        #pragma unroll
        for (int k = 0; k < 6; k++) {
            const int d = warp + 8 * k;
            float4 v = *reinterpret_cast<const float4*>(&St[(MAXD - d) * SP + iq]);
            v.x *= scale; v.y *= scale; v.z *= scale; v.w *= scale;
            *reinterpret_cast<float4*>(
                out + (((size_t)b * MAXD + d) * HDIM + h) * WDIM + w0 + iq) = v;
        }
        // ordering: next iteration's post-wait __syncthreads separates these St
        // reads from the next scatter; cp.async refill of buffer p (issued next
        // iteration, pre-barrier) cannot race this iteration's MMA reads since
        // those precede the pre-gather barrier all threads passed.
    }
}

extern "C" void kernel_launch(void* const* d_in, const int* in_sizes, int n_in,
                              void* d_out, int out_size) {
    const float* x = (const float*)d_in[0];
    const float* y = (const float*)d_in[1];
    float* out = (float*)d_out;

    cudaFuncSetAttribute(corr_mma,
                         cudaFuncAttributeMaxDynamicSharedMemorySize, SMEM_BYTES);

    dim3 grid(WDIM / MT, HDIM / HC, BDIM);   // (4, 32, 8) = 1024 blocks
    corr_mma<<<grid, NTHR, SMEM_BYTES>>>(x, y, out);
}